// round 4
// baseline (speedup 1.0000x reference)
#include <cuda_runtime.h>
#include <cuda_fp16.h>
#include <cstdint>

// Problem constants: N=100000, S=8, B=4, F=128, O=64, E=3.2M
#define MAXN 100000
#define FDIM 128
#define ODIM 64
#define NBAS 4
#define NREL 8

// Scratch (__device__ globals; no runtime alloc allowed)
__device__ __half g_FWh[(size_t)NREL * MAXN * ODIM];  // [8, N, 64] fp16 (102.4 MB)
__device__ float  g_W[NREL * ODIM * FDIM];            // [8][n=64][k=128] tf32-rounded bits

// ---------------------------------------------------------------------------
__device__ __forceinline__ uint32_t f2tf32(float v) {
    uint32_t t;
    asm("cvt.rna.tf32.f32 %0, %1;" : "=r"(t) : "f"(v));
    return t;
}

__device__ __forceinline__ void mma_tf32(float* d, uint32_t a0, uint32_t a1, uint32_t a2,
                                         uint32_t a3, uint32_t b0, uint32_t b1) {
    asm volatile(
        "mma.sync.aligned.m16n8k8.row.col.f32.tf32.tf32.f32 "
        "{%0,%1,%2,%3}, {%4,%5,%6,%7}, {%8,%9}, {%0,%1,%2,%3};"
        : "+f"(d[0]), "+f"(d[1]), "+f"(d[2]), "+f"(d[3])
        : "r"(a0), "r"(a1), "r"(a2), "r"(a3), "r"(b0), "r"(b1));
}

// ---------------------------------------------------------------------------
// Kernel 0: W[s][n][k] = tf32( sum_b comp[s,b] * Bases[b][k][n] )
// ---------------------------------------------------------------------------
__global__ void wcomb_kernel(const float* __restrict__ bases, const float* __restrict__ comp) {
    int idx = blockIdx.x * blockDim.x + threadIdx.x;
    if (idx >= NREL * FDIM * ODIM) return;
    int s = idx >> 13;
    int r = idx & 8191;
    int n = r >> 7;            // 0..63  (output col)
    int k = r & 127;           // 0..127 (input feat)
    float acc = 0.f;
    #pragma unroll
    for (int b = 0; b < NBAS; b++)
        acc += __ldg(comp + s * NBAS + b) * __ldg(bases + b * FDIM * ODIM + k * ODIM + n);
    g_W[idx] = __uint_as_float(f2tf32(acc));
}

// ---------------------------------------------------------------------------
// Kernel 1: FW[s] = X @ W[s]^T (tf32 mma, X hi/lo split), fp16 output.
// Block: 256 threads (8 warps). Tile: 128 rows x 64 cols, K=128.
// Warp w owns rows w*16..w*16+15. smem = Xs[128][132] + Ws[64][132] = 101376 B
// -> 2 blocks/SM (16 warps/SM), fixes the round-3 occupancy stall.
// ---------------------------------------------------------------------------
#define XS_STRIDE 132
#define WS_STRIDE 132
#define SMEM_GEMM (128 * XS_STRIDE * 4 + 64 * WS_STRIDE * 4)

__global__ void __launch_bounds__(256) gemm_fw_kernel(const float* __restrict__ X, int nN) {
    extern __shared__ float sm[];
    float* Xs = sm;                         // [128][132] fp32
    float* Ws = sm + 128 * XS_STRIDE;       // [64][132]  tf32 bits

    const int tid = threadIdx.x;
    const int wid = tid >> 5;
    const int lane = tid & 31;
    const int g = lane >> 2;                // 0..7
    const int tg = lane & 3;                // 0..3
    const int node0 = blockIdx.x * 128;
    const int wrow = wid * 16;

    // Load X tile [128 x 128] fp32 (coalesced float4)
    {
        const float4* X4 = (const float4*)X;
        #pragma unroll 4
        for (int i = tid; i < 4096; i += 256) {
            int row = i >> 5, q = i & 31;
            int gn = node0 + row;
            float4 v = (gn < nN) ? X4[(size_t)gn * 32 + q] : make_float4(0.f, 0.f, 0.f, 0.f);
            *(float4*)(Xs + row * XS_STRIDE + q * 4) = v;
        }
    }

    for (int s = 0; s < NREL; s++) {
        __syncthreads();   // prior iter's Ws reads done (also publishes Xs on s=0)
        // Load W_s [64][128] -> padded smem
        {
            const float4* src = (const float4*)(g_W + s * ODIM * FDIM);
            #pragma unroll
            for (int i = tid; i < 2048; i += 256) {
                int n = i >> 5, q = i & 31;
                *(float4*)(Ws + n * WS_STRIDE + q * 4) = src[i];
            }
        }
        __syncthreads();

        float d[8][4];
        #pragma unroll
        for (int ni = 0; ni < 8; ni++)
            #pragma unroll
            for (int j = 0; j < 4; j++) d[ni][j] = 0.f;

        #pragma unroll 2
        for (int ks = 0; ks < 16; ks++) {
            // A fragments, hi/lo split (rows g, g+8 within warp's 16-row slab)
            const float* ar = Xs + (wrow + g) * XS_STRIDE + ks * 8 + tg;
            float x0 = ar[0];
            float x1 = ar[8 * XS_STRIDE];
            float x2 = ar[4];
            float x3 = ar[8 * XS_STRIDE + 4];
            uint32_t ah0 = f2tf32(x0), ah1 = f2tf32(x1), ah2 = f2tf32(x2), ah3 = f2tf32(x3);
            uint32_t al0 = f2tf32(x0 - __uint_as_float(ah0));
            uint32_t al1 = f2tf32(x1 - __uint_as_float(ah1));
            uint32_t al2 = f2tf32(x2 - __uint_as_float(ah2));
            uint32_t al3 = f2tf32(x3 - __uint_as_float(ah3));
            #pragma unroll
            for (int ni = 0; ni < 8; ni++) {
                const float* br = Ws + (ni * 8 + g) * WS_STRIDE + ks * 8 + tg;
                uint32_t b0 = __float_as_uint(br[0]);
                uint32_t b1 = __float_as_uint(br[4]);
                mma_tf32(d[ni], ah0, ah1, ah2, ah3, b0, b1);
                mma_tf32(d[ni], al0, al1, al2, al3, b0, b1);
            }
        }

        // fp16 epilogue: c0,c1 at (row wrow+g, col ni*8+tg*2); c2,c3 at row+8
        {
            __half* fwbase = g_FWh + (size_t)s * nN * ODIM;
            int r0 = node0 + wrow + g;
            int r1 = r0 + 8;
            #pragma unroll
            for (int ni = 0; ni < 8; ni++) {
                int c = ni * 8 + tg * 2;
                if (r0 < nN)
                    *(__half2*)(fwbase + (size_t)r0 * ODIM + c) = __floats2half2_rn(d[ni][0], d[ni][1]);
                if (r1 < nN)
                    *(__half2*)(fwbase + (size_t)r1 * ODIM + c) = __floats2half2_rn(d[ni][2], d[ni][3]);
            }
        }
    }
}

// ---------------------------------------------------------------------------
// Kernel 2: SpMM scatter: out[rows[e]] += vals[e] * FW[cols[e]] (fp16 gather)
// 8 threads per edge: each loads 16B (8 halves), converts, 2x red.v4.f32
// ---------------------------------------------------------------------------
__global__ void spmm_kernel(const int* __restrict__ rows, const int* __restrict__ cols,
                            const float* __restrict__ vals, float* __restrict__ out, int E) {
    int t = blockIdx.x * blockDim.x + threadIdx.x;
    int e = t >> 3;
    if (e >= E) return;
    int l = t & 7;
    int c = __ldg(cols + e);
    int r = __ldg(rows + e);
    float v = __ldg(vals + e);

    const uint4* src = (const uint4*)(g_FWh + (size_t)c * ODIM) + l;
    uint4 p = *src;
    float2 f0 = __half22float2(*(__half2*)&p.x);
    float2 f1 = __half22float2(*(__half2*)&p.y);
    float2 f2 = __half22float2(*(__half2*)&p.z);
    float2 f3 = __half22float2(*(__half2*)&p.w);

    float* dst = out + (size_t)r * ODIM + l * 8;
    asm volatile("red.global.add.v4.f32 [%0], {%1,%2,%3,%4};"
                 :: "l"(dst), "f"(f0.x * v), "f"(f0.y * v), "f"(f1.x * v), "f"(f1.y * v) : "memory");
    asm volatile("red.global.add.v4.f32 [%0], {%1,%2,%3,%4};"
                 :: "l"(dst + 4), "f"(f2.x * v), "f"(f2.y * v), "f"(f3.x * v), "f"(f3.y * v) : "memory");
}

// ---------------------------------------------------------------------------
// Kernel 3: out = relu(out + bias)
// ---------------------------------------------------------------------------
__global__ void bias_relu_kernel(float* __restrict__ out, const float* __restrict__ bias, int nN) {
    int idx = blockIdx.x * blockDim.x + threadIdx.x;
    int total = nN * 16;
    if (idx >= total) return;
    float4 v = ((float4*)out)[idx];
    int og = idx & 15;
    float4 bb = __ldg((const float4*)bias + og);
    v.x = fmaxf(v.x + bb.x, 0.f);
    v.y = fmaxf(v.y + bb.y, 0.f);
    v.z = fmaxf(v.z + bb.z, 0.f);
    v.w = fmaxf(v.w + bb.w, 0.f);
    ((float4*)out)[idx] = v;
}

// ---------------------------------------------------------------------------
extern "C" void kernel_launch(void* const* d_in, const int* in_sizes, int n_in,
                              void* d_out, int out_size) {
    const float* X     = (const float*)d_in[0];   // [N, 128]
    const int*   rows  = (const int*)  d_in[1];   // [E]
    const int*   cols  = (const int*)  d_in[2];   // [E]
    const float* vals  = (const float*)d_in[3];   // [E]
    const float* bases = (const float*)d_in[4];   // [4, 128, 64]
    const float* comp  = (const float*)d_in[5];   // [8, 4]
    const float* bias  = (const float*)d_in[6];   // [64]
    float* out = (float*)d_out;                   // [N, 64]

    int nN = in_sizes[0] / FDIM;
    int E  = in_sizes[1];

    cudaFuncSetAttribute(gemm_fw_kernel, cudaFuncAttributeMaxDynamicSharedMemorySize, SMEM_GEMM);

    cudaMemsetAsync(out, 0, (size_t)nN * ODIM * sizeof(float));

    wcomb_kernel<<<(NREL * FDIM * ODIM + 255) / 256, 256>>>(bases, comp);

    int gblocks = (nN + 127) / 128;
    gemm_fw_kernel<<<gblocks, 256, SMEM_GEMM>>>(X, nN);

    long long spthreads = (long long)E * 8;
    spmm_kernel<<<(int)((spthreads + 255) / 256), 256>>>(rows, cols, vals, out, E);

    bias_relu_kernel<<<(nN * 16 + 255) / 256, 256>>>(out, bias, nN);
}

// round 5
// speedup vs baseline: 1.1707x; 1.1707x over previous
#include <cuda_runtime.h>
#include <cuda_fp16.h>
#include <cstdint>

// Problem constants: N=100000, S=8, B=4, F=128, O=64, E=3.2M
#define MAXN 100000
#define FDIM 128
#define ODIM 64
#define NBAS 4
#define NREL 8

// Scratch (__device__ globals; no runtime alloc allowed)
__device__ __half g_FWh[(size_t)NREL * MAXN * ODIM];  // [8, N, 64] fp16 (102.4 MB)
__device__ float  g_W[NREL * ODIM * FDIM];            // [8][n=64][k=128] tf32-rounded bits

// ---------------------------------------------------------------------------
__device__ __forceinline__ uint32_t f2tf32(float v) {
    uint32_t t;
    asm("cvt.rna.tf32.f32 %0, %1;" : "=r"(t) : "f"(v));
    return t;
}

__device__ __forceinline__ void mma_tf32(float* d, uint32_t a0, uint32_t a1, uint32_t a2,
                                         uint32_t a3, uint32_t b0, uint32_t b1) {
    asm volatile(
        "mma.sync.aligned.m16n8k8.row.col.f32.tf32.tf32.f32 "
        "{%0,%1,%2,%3}, {%4,%5,%6,%7}, {%8,%9}, {%0,%1,%2,%3};"
        : "+f"(d[0]), "+f"(d[1]), "+f"(d[2]), "+f"(d[3])
        : "r"(a0), "r"(a1), "r"(a2), "r"(a3), "r"(b0), "r"(b1));
}

// ---------------------------------------------------------------------------
// Kernel 0: W[s][n][k] = tf32( sum_b comp[s,b] * Bases[b][k][n] )
// ---------------------------------------------------------------------------
__global__ void wcomb_kernel(const float* __restrict__ bases, const float* __restrict__ comp) {
    int idx = blockIdx.x * blockDim.x + threadIdx.x;
    if (idx >= NREL * FDIM * ODIM) return;
    int s = idx >> 13;
    int r = idx & 8191;
    int n = r >> 7;            // 0..63  (output col)
    int k = r & 127;           // 0..127 (input feat)
    float acc = 0.f;
    #pragma unroll
    for (int b = 0; b < NBAS; b++)
        acc += __ldg(comp + s * NBAS + b) * __ldg(bases + b * FDIM * ODIM + k * ODIM + n);
    g_W[idx] = __uint_as_float(f2tf32(acc));
}

// ---------------------------------------------------------------------------
// Kernel 1: FW[s] = X @ W[s]^T, single-tf32 mma (no hi/lo split), fp16 output.
// Block: 256 threads (8 warps), tile 128 rows x 64 cols, K=128.
// smem = Xs[128][132] + Ws[64][132] = 101376 B -> 2 blocks/SM.
// MMA count halved vs round 4: the measured binding resource.
// ---------------------------------------------------------------------------
#define XS_STRIDE 132
#define WS_STRIDE 132
#define SMEM_GEMM (128 * XS_STRIDE * 4 + 64 * WS_STRIDE * 4)

__global__ void __launch_bounds__(256) gemm_fw_kernel(const float* __restrict__ X, int nN) {
    extern __shared__ float sm[];
    float* Xs = sm;                         // [128][132] tf32 bits (pre-rounded at load)
    float* Ws = sm + 128 * XS_STRIDE;       // [64][132]  tf32 bits

    const int tid = threadIdx.x;
    const int wid = tid >> 5;
    const int lane = tid & 31;
    const int g = lane >> 2;                // 0..7
    const int tg = lane & 3;                // 0..3
    const int node0 = blockIdx.x * 128;
    const int wrow = wid * 16;

    // Load X tile [128 x 128], round to tf32 ONCE at load time
    {
        const float4* X4 = (const float4*)X;
        #pragma unroll 4
        for (int i = tid; i < 4096; i += 256) {
            int row = i >> 5, q = i & 31;
            int gn = node0 + row;
            float4 v = (gn < nN) ? X4[(size_t)gn * 32 + q] : make_float4(0.f, 0.f, 0.f, 0.f);
            uint4 t;
            t.x = f2tf32(v.x); t.y = f2tf32(v.y); t.z = f2tf32(v.z); t.w = f2tf32(v.w);
            *(uint4*)(Xs + row * XS_STRIDE + q * 4) = t;
        }
    }

    for (int s = 0; s < NREL; s++) {
        __syncthreads();   // prior iter's Ws reads done (also publishes Xs on s=0)
        {
            const float4* src = (const float4*)(g_W + s * ODIM * FDIM);
            #pragma unroll
            for (int i = tid; i < 2048; i += 256) {
                int n = i >> 5, q = i & 31;
                *(float4*)(Ws + n * WS_STRIDE + q * 4) = src[i];
            }
        }
        __syncthreads();

        float d[8][4];
        #pragma unroll
        for (int ni = 0; ni < 8; ni++)
            #pragma unroll
            for (int j = 0; j < 4; j++) d[ni][j] = 0.f;

        #pragma unroll 2
        for (int ks = 0; ks < 16; ks++) {
            const float* ar = Xs + (wrow + g) * XS_STRIDE + ks * 8 + tg;
            uint32_t a0 = __float_as_uint(ar[0]);
            uint32_t a1 = __float_as_uint(ar[8 * XS_STRIDE]);
            uint32_t a2 = __float_as_uint(ar[4]);
            uint32_t a3 = __float_as_uint(ar[8 * XS_STRIDE + 4]);
            #pragma unroll
            for (int ni = 0; ni < 8; ni++) {
                const float* br = Ws + (ni * 8 + g) * WS_STRIDE + ks * 8 + tg;
                uint32_t b0 = __float_as_uint(br[0]);
                uint32_t b1 = __float_as_uint(br[4]);
                mma_tf32(d[ni], a0, a1, a2, a3, b0, b1);
            }
        }

        // fp16 epilogue: c0,c1 at (row wrow+g, col ni*8+tg*2); c2,c3 at row+8
        {
            __half* fwbase = g_FWh + (size_t)s * nN * ODIM;
            int r0 = node0 + wrow + g;
            int r1 = r0 + 8;
            #pragma unroll
            for (int ni = 0; ni < 8; ni++) {
                int c = ni * 8 + tg * 2;
                if (r0 < nN)
                    *(__half2*)(fwbase + (size_t)r0 * ODIM + c) = __floats2half2_rn(d[ni][0], d[ni][1]);
                if (r1 < nN)
                    *(__half2*)(fwbase + (size_t)r1 * ODIM + c) = __floats2half2_rn(d[ni][2], d[ni][3]);
            }
        }
    }
}

// ---------------------------------------------------------------------------
// Kernel 2: SpMM scatter: out[rows[e]] += vals[e] * FW[cols[e]] (fp16 gather)
// 8 threads per edge: 16B load each, 2x red.v4.f32
// ---------------------------------------------------------------------------
__global__ void spmm_kernel(const int* __restrict__ rows, const int* __restrict__ cols,
                            const float* __restrict__ vals, float* __restrict__ out, int E) {
    int t = blockIdx.x * blockDim.x + threadIdx.x;
    int e = t >> 3;
    if (e >= E) return;
    int l = t & 7;
    int c = __ldg(cols + e);
    int r = __ldg(rows + e);
    float v = __ldg(vals + e);

    const uint4* src = (const uint4*)(g_FWh + (size_t)c * ODIM) + l;
    uint4 p = *src;
    float2 f0 = __half22float2(*(__half2*)&p.x);
    float2 f1 = __half22float2(*(__half2*)&p.y);
    float2 f2 = __half22float2(*(__half2*)&p.z);
    float2 f3 = __half22float2(*(__half2*)&p.w);

    float* dst = out + (size_t)r * ODIM + l * 8;
    asm volatile("red.global.add.v4.f32 [%0], {%1,%2,%3,%4};"
                 :: "l"(dst), "f"(f0.x * v), "f"(f0.y * v), "f"(f1.x * v), "f"(f1.y * v) : "memory");
    asm volatile("red.global.add.v4.f32 [%0], {%1,%2,%3,%4};"
                 :: "l"(dst + 4), "f"(f2.x * v), "f"(f2.y * v), "f"(f3.x * v), "f"(f3.y * v) : "memory");
}

// ---------------------------------------------------------------------------
// Kernel 3: out = relu(out + bias)
// ---------------------------------------------------------------------------
__global__ void bias_relu_kernel(float* __restrict__ out, const float* __restrict__ bias, int nN) {
    int idx = blockIdx.x * blockDim.x + threadIdx.x;
    int total = nN * 16;
    if (idx >= total) return;
    float4 v = ((float4*)out)[idx];
    int og = idx & 15;
    float4 bb = __ldg((const float4*)bias + og);
    v.x = fmaxf(v.x + bb.x, 0.f);
    v.y = fmaxf(v.y + bb.y, 0.f);
    v.z = fmaxf(v.z + bb.z, 0.f);
    v.w = fmaxf(v.w + bb.w, 0.f);
    ((float4*)out)[idx] = v;
}

// ---------------------------------------------------------------------------
extern "C" void kernel_launch(void* const* d_in, const int* in_sizes, int n_in,
                              void* d_out, int out_size) {
    const float* X     = (const float*)d_in[0];   // [N, 128]
    const int*   rows  = (const int*)  d_in[1];   // [E]
    const int*   cols  = (const int*)  d_in[2];   // [E]
    const float* vals  = (const float*)d_in[3];   // [E]
    const float* bases = (const float*)d_in[4];   // [4, 128, 64]
    const float* comp  = (const float*)d_in[5];   // [8, 4]
    const float* bias  = (const float*)d_in[6];   // [64]
    float* out = (float*)d_out;                   // [N, 64]

    int nN = in_sizes[0] / FDIM;
    int E  = in_sizes[1];

    cudaFuncSetAttribute(gemm_fw_kernel, cudaFuncAttributeMaxDynamicSharedMemorySize, SMEM_GEMM);

    cudaMemsetAsync(out, 0, (size_t)nN * ODIM * sizeof(float));

    wcomb_kernel<<<(NREL * FDIM * ODIM + 255) / 256, 256>>>(bases, comp);

    int gblocks = (nN + 127) / 128;
    gemm_fw_kernel<<<gblocks, 256, SMEM_GEMM>>>(X, nN);

    long long spthreads = (long long)E * 8;
    spmm_kernel<<<(int)((spthreads + 255) / 256), 256>>>(rows, cols, vals, out, E);

    bias_relu_kernel<<<(nN * 16 + 255) / 256, 256>>>(out, bias, nN);
}

// round 6
// speedup vs baseline: 1.3394x; 1.1441x over previous
#include <cuda_runtime.h>
#include <cuda_fp16.h>
#include <cstdint>

// Problem constants: N=100000, S=8, B=4, F=128, O=64, E=3.2M
#define MAXN 100000
#define FDIM 128
#define ODIM 64
#define NBAS 4
#define NREL 8

// Scratch (__device__ globals; no runtime alloc allowed)
__device__ __half g_FWh[(size_t)NREL * MAXN * ODIM];  // [8, N, 64] fp16 (102.4 MB)
__device__ __half g_Wh[NREL * ODIM * FDIM];           // [8][n=64][k=128] fp16

// ---------------------------------------------------------------------------
__device__ __forceinline__ void mma_f16(float* d, uint32_t a0, uint32_t a1, uint32_t a2,
                                        uint32_t a3, uint32_t b0, uint32_t b1) {
    asm volatile(
        "mma.sync.aligned.m16n8k16.row.col.f32.f16.f16.f32 "
        "{%0,%1,%2,%3}, {%4,%5,%6,%7}, {%8,%9}, {%0,%1,%2,%3};"
        : "+f"(d[0]), "+f"(d[1]), "+f"(d[2]), "+f"(d[3])
        : "r"(a0), "r"(a1), "r"(a2), "r"(a3), "r"(b0), "r"(b1));
}

// ---------------------------------------------------------------------------
// Kernel 0: W[s][n][k] = fp16( sum_b comp[s,b] * Bases[b][k][n] )
// ---------------------------------------------------------------------------
__global__ void wcomb_kernel(const float* __restrict__ bases, const float* __restrict__ comp) {
    int idx = blockIdx.x * blockDim.x + threadIdx.x;
    if (idx >= NREL * FDIM * ODIM) return;
    int s = idx >> 13;
    int r = idx & 8191;
    int n = r >> 7;            // 0..63  (output col)
    int k = r & 127;           // 0..127 (input feat)
    float acc = 0.f;
    #pragma unroll
    for (int b = 0; b < NBAS; b++)
        acc += __ldg(comp + s * NBAS + b) * __ldg(bases + b * FDIM * ODIM + k * ODIM + n);
    g_Wh[idx] = __float2half_rn(acc);
}

// ---------------------------------------------------------------------------
// Kernel 1: FW[s] = X @ W[s]^T via fp16 mma (f32 accumulate), fp16 output.
// Block: 256 threads (8 warps), tile 128 rows x 64 cols, K=128.
// smem (halves): Xs[128][136] + Ws[64][136] = 69632 + 17408 = 87040 B
//   -> 2 blocks/SM. Stride 136 halves => bank (4g+tg)%32, conflict-free.
// ---------------------------------------------------------------------------
#define XS_STRIDE 136
#define WS_STRIDE 136
#define SMEM_GEMM (128 * XS_STRIDE * 2 + 64 * WS_STRIDE * 2)

__global__ void __launch_bounds__(256) gemm_fw_kernel(const float* __restrict__ X, int nN) {
    extern __shared__ __half smh[];
    __half* Xs = smh;                       // [128][136]
    __half* Ws = smh + 128 * XS_STRIDE;     // [64][136]

    const int tid = threadIdx.x;
    const int wid = tid >> 5;
    const int lane = tid & 31;
    const int g = lane >> 2;                // 0..7
    const int tg = lane & 3;                // 0..3
    const int node0 = blockIdx.x * 128;
    const int wrow = wid * 16;

    // Load X tile [128 x 128] fp32 -> fp16 smem
    {
        const float4* X4 = (const float4*)X;
        #pragma unroll 4
        for (int i = tid; i < 4096; i += 256) {
            int row = i >> 5, q = i & 31;
            int gn = node0 + row;
            float4 v = (gn < nN) ? X4[(size_t)gn * 32 + q] : make_float4(0.f, 0.f, 0.f, 0.f);
            __half2 h0 = __floats2half2_rn(v.x, v.y);
            __half2 h1 = __floats2half2_rn(v.z, v.w);
            uint2 packed = make_uint2(*(uint32_t*)&h0, *(uint32_t*)&h1);
            *(uint2*)(Xs + row * XS_STRIDE + q * 4) = packed;
        }
    }

    for (int s = 0; s < NREL; s++) {
        __syncthreads();   // prior iter's Ws reads done (also publishes Xs on s=0)
        // Load W_s [64][128] fp16 (1024 uint4)
        {
            const uint4* src = (const uint4*)(g_Wh + s * ODIM * FDIM);
            #pragma unroll
            for (int i = tid; i < 1024; i += 256) {
                int n = i >> 4, q = i & 15;          // q: uint4 index (8 halves)
                *(uint4*)(Ws + n * WS_STRIDE + q * 8) = src[i];
            }
        }
        __syncthreads();

        float d[8][4];
        #pragma unroll
        for (int ni = 0; ni < 8; ni++)
            #pragma unroll
            for (int j = 0; j < 4; j++) d[ni][j] = 0.f;

        #pragma unroll
        for (int ks = 0; ks < 8; ks++) {
            // A fragments (m16n8k16): rows wrow+g / wrow+g+8, k halves ks*16+tg*2 (+8)
            const __half* ar = Xs + (wrow + g) * XS_STRIDE + ks * 16 + tg * 2;
            uint32_t a0 = *(const uint32_t*)(ar);
            uint32_t a1 = *(const uint32_t*)(ar + 8 * XS_STRIDE);
            uint32_t a2 = *(const uint32_t*)(ar + 8);
            uint32_t a3 = *(const uint32_t*)(ar + 8 * XS_STRIDE + 8);
            #pragma unroll
            for (int ni = 0; ni < 8; ni++) {
                const __half* br = Ws + (ni * 8 + g) * WS_STRIDE + ks * 16 + tg * 2;
                uint32_t b0 = *(const uint32_t*)(br);
                uint32_t b1 = *(const uint32_t*)(br + 8);
                mma_f16(d[ni], a0, a1, a2, a3, b0, b1);
            }
        }

        // fp16 epilogue: c0,c1 at (row wrow+g, col ni*8+tg*2); c2,c3 at row+8
        {
            __half* fwbase = g_FWh + (size_t)s * nN * ODIM;
            int r0 = node0 + wrow + g;
            int r1 = r0 + 8;
            #pragma unroll
            for (int ni = 0; ni < 8; ni++) {
                int c = ni * 8 + tg * 2;
                if (r0 < nN)
                    *(__half2*)(fwbase + (size_t)r0 * ODIM + c) = __floats2half2_rn(d[ni][0], d[ni][1]);
                if (r1 < nN)
                    *(__half2*)(fwbase + (size_t)r1 * ODIM + c) = __floats2half2_rn(d[ni][2], d[ni][3]);
            }
        }
    }
}

// ---------------------------------------------------------------------------
// Kernel 2: SpMM scatter: out[rows[e]] += vals[e] * FW[cols[e]] (fp16 gather)
// 8 threads per edge: 16B load each, 2x red.v4.f32
// ---------------------------------------------------------------------------
__global__ void spmm_kernel(const int* __restrict__ rows, const int* __restrict__ cols,
                            const float* __restrict__ vals, float* __restrict__ out, int E) {
    int t = blockIdx.x * blockDim.x + threadIdx.x;
    int e = t >> 3;
    if (e >= E) return;
    int l = t & 7;
    int c = __ldg(cols + e);
    int r = __ldg(rows + e);
    float v = __ldg(vals + e);

    const uint4* src = (const uint4*)(g_FWh + (size_t)c * ODIM) + l;
    uint4 p = *src;
    float2 f0 = __half22float2(*(__half2*)&p.x);
    float2 f1 = __half22float2(*(__half2*)&p.y);
    float2 f2 = __half22float2(*(__half2*)&p.z);
    float2 f3 = __half22float2(*(__half2*)&p.w);

    float* dst = out + (size_t)r * ODIM + l * 8;
    asm volatile("red.global.add.v4.f32 [%0], {%1,%2,%3,%4};"
                 :: "l"(dst), "f"(f0.x * v), "f"(f0.y * v), "f"(f1.x * v), "f"(f1.y * v) : "memory");
    asm volatile("red.global.add.v4.f32 [%0], {%1,%2,%3,%4};"
                 :: "l"(dst + 4), "f"(f2.x * v), "f"(f2.y * v), "f"(f3.x * v), "f"(f3.y * v) : "memory");
}

// ---------------------------------------------------------------------------
// Kernel 3: out = relu(out + bias)
// ---------------------------------------------------------------------------
__global__ void bias_relu_kernel(float* __restrict__ out, const float* __restrict__ bias, int nN) {
    int idx = blockIdx.x * blockDim.x + threadIdx.x;
    int total = nN * 16;
    if (idx >= total) return;
    float4 v = ((float4*)out)[idx];
    int og = idx & 15;
    float4 bb = __ldg((const float4*)bias + og);
    v.x = fmaxf(v.x + bb.x, 0.f);
    v.y = fmaxf(v.y + bb.y, 0.f);
    v.z = fmaxf(v.z + bb.z, 0.f);
    v.w = fmaxf(v.w + bb.w, 0.f);
    ((float4*)out)[idx] = v;
}

// ---------------------------------------------------------------------------
extern "C" void kernel_launch(void* const* d_in, const int* in_sizes, int n_in,
                              void* d_out, int out_size) {
    const float* X     = (const float*)d_in[0];   // [N, 128]
    const int*   rows  = (const int*)  d_in[1];   // [E]
    const int*   cols  = (const int*)  d_in[2];   // [E]
    const float* vals  = (const float*)d_in[3];   // [E]
    const float* bases = (const float*)d_in[4];   // [4, 128, 64]
    const float* comp  = (const float*)d_in[5];   // [8, 4]
    const float* bias  = (const float*)d_in[6];   // [64]
    float* out = (float*)d_out;                   // [N, 64]

    int nN = in_sizes[0] / FDIM;
    int E  = in_sizes[1];

    cudaFuncSetAttribute(gemm_fw_kernel, cudaFuncAttributeMaxDynamicSharedMemorySize, SMEM_GEMM);

    cudaMemsetAsync(out, 0, (size_t)nN * ODIM * sizeof(float));

    wcomb_kernel<<<(NREL * FDIM * ODIM + 255) / 256, 256>>>(bases, comp);

    int gblocks = (nN + 127) / 128;
    gemm_fw_kernel<<<gblocks, 256, SMEM_GEMM>>>(X, nN);

    long long spthreads = (long long)E * 8;
    spmm_kernel<<<(int)((spthreads + 255) / 256), 256>>>(rows, cols, vals, out, E);

    bias_relu_kernel<<<(nN * 16 + 255) / 256, 256>>>(out, bias, nN);
}